// round 7
// baseline (speedup 1.0000x reference)
#include <cuda_runtime.h>
#include <cuda_bf16.h>
#include <math.h>

// Problem constants
static constexpr int NB = 4096;   // batch
static constexpr int NL = 16;     // seq length
static constexpr int NH = 256;    // hidden
static constexpr int NLAT = 64;   // latent
static constexpr int NV = 800;    // vocab
static constexpr int STEPS = NL - 1;  // 15
static constexpr int MT = 32;     // rows per CTA (M tile)

// ---------------- packed f32x2 helpers ----------------
#define FFMA2(acc, a, b) asm("fma.rn.f32x2 %0, %1, %2, %0;" : "+l"(acc) : "l"(a), "l"(b))

static __device__ __forceinline__ float2 unpack2(unsigned long long v) {
    float2 f;
    asm("mov.b64 {%0, %1}, %2;" : "=f"(f.x), "=f"(f.y) : "l"(v));
    return f;
}

// ---------------- device scratch (allocation-free) ----------------
__device__ float g_mfwd[STEPS * NB * NH];
__device__ float g_mrev[STEPS * NB * NH];
__device__ float g_rm0[NB * NH];            // fwd carry r*m
__device__ float g_rm1[NB * NH];            // rev carry r*m
// pair-interleaved weights: float index ((k>>2)*J + col)*4 + (k&3), as ulonglong2
__device__ ulonglong2 g_Wz4[512 * 256 / 4];
__device__ ulonglong2 g_Wh4[512 * 256 / 4];
__device__ ulonglong2 g_C4 [512 * 256 / 4];   // [Wr ; Ur]
__device__ ulonglong2 g_Wq4[320 * 256 / 4];
__device__ ulonglong2 g_Up4[576 * 256 / 4];
__device__ ulonglong2 g_Wo4[256 * 800 / 4];
__device__ double g_qloss, g_ploss;
__device__ unsigned long long g_qcnt, g_pcnt;

// ---------------- init ----------------
__global__ void k_init() {
    if (threadIdx.x == 0) {
        g_qloss = 0.0; g_ploss = 0.0; g_qcnt = 0ULL; g_pcnt = 0ULL;
    }
}

// ---------------- repack: src[J][K] row-major -> dst interleaved ----------------
__global__ void k_repack(const float* __restrict__ src, int J, int K, int which, int koff) {
    float* dst;
    switch (which) {
        case 0: dst = (float*)g_Wz4; break;
        case 1: dst = (float*)g_Wh4; break;
        case 2: dst = (float*)g_C4;  break;
        case 3: dst = (float*)g_Wq4; break;
        case 4: dst = (float*)g_Up4; break;
        default: dst = (float*)g_Wo4; break;
    }
    int idx = blockIdx.x * blockDim.x + threadIdx.x;
    if (idx < J * K) {
        int jcol = idx / K, k = idx % K;
        int kk = k + koff;
        dst[((kk >> 2) * J + jcol) * 4 + (kk & 3)] = src[jcol * K + k];
    }
}

// ---------------- fused fwd+rev GRU step ----------------
// blockIdx < 128: fwd step; blockIdx >= 128: rev step (independent chains)
__global__ __launch_bounds__(512, 1) void k_gru(const int* __restrict__ wid,
                                                const float* __restrict__ emb,
                                                const float* __restrict__ bz,
                                                const float* __restrict__ bh,
                                                const float* __restrict__ br,
                                                int step) {
    extern __shared__ __align__(16) float dyn[];
    float (*sx)[NH] = (float(*)[NH])dyn;
    float (*sm)[NH] = (float(*)[NH])(dyn + MT * NH);
    float (*sr)[NH] = (float(*)[NH])(dyn + 2 * MT * NH);

    const int tid = threadIdx.x;
    const int j = tid & 255;
    const int rh = tid >> 8;           // 0/1 row-half
    const int dir = blockIdx.x >> 7;   // 0 fwd, 1 rev
    const int row0 = (blockIdx.x & 127) * MT;

    int ts, td;
    const float* m_prev;
    float* m_out;
    float* rmbuf;
    if (dir == 0) {
        ts = step; td = step + 1;
        m_prev = (step == 0) ? nullptr : &g_mfwd[(step - 1) * NB * NH];
        m_out = &g_mfwd[step * NB * NH];
        rmbuf = g_rm0;
    } else {
        ts = 15 - step; td = 14 - step;
        m_prev = (step == 0) ? nullptr : &g_mrev[(15 - step) * NB * NH];
        m_out = &g_mrev[(14 - step) * NB * NH];
        rmbuf = g_rm1;
    }

    // stage: each thread fills its 16 rows (row-half) for its column j
    #pragma unroll
    for (int rl = 0; rl < 16; rl++) {
        int rg = rh * 16 + rl;
        int b = row0 + rg;
        int w = wid[b * NL + ts];
        sx[rg][j] = emb[w * NH + j];
        if (m_prev) { sm[rg][j] = m_prev[b * NH + j]; sr[rg][j] = rmbuf[b * NH + j]; }
        else        { sm[rg][j] = 0.f;                sr[rg][j] = 0.f; }
    }
    __syncthreads();

    const ulonglong2* SX = (const ulonglong2*)sx;   // [rg*64 + kk]
    const ulonglong2* SM = (const ulonglong2*)sm;
    const ulonglong2* SR = (const ulonglong2*)sr;
    const int rbase = rh * 16 * 64;

    // ---- Z = sigmoid([x|m] @ WzT + bz) ----
    unsigned long long acc2[16];
    #pragma unroll
    for (int r = 0; r < 16; r++) acc2[r] = 0ULL;
    #pragma unroll 2
    for (int kk = 0; kk < 64; kk++) {
        ulonglong2 w = g_Wz4[kk * NH + j];
        #pragma unroll
        for (int r = 0; r < 16; r++) {
            ulonglong2 a = SX[rbase + r * 64 + kk];
            FFMA2(acc2[r], a.x, w.x);
            FFMA2(acc2[r], a.y, w.y);
        }
    }
    #pragma unroll 2
    for (int kk = 0; kk < 64; kk++) {
        ulonglong2 w = g_Wz4[(64 + kk) * NH + j];
        #pragma unroll
        for (int r = 0; r < 16; r++) {
            ulonglong2 a = SM[rbase + r * 64 + kk];
            FFMA2(acc2[r], a.x, w.x);
            FFMA2(acc2[r], a.y, w.y);
        }
    }
    float zg[16];
    const float bzv = bz[j];
    #pragma unroll
    for (int r = 0; r < 16; r++) {
        float2 t = unpack2(acc2[r]);
        zg[r] = 1.f / (1.f + expf(-(t.x + t.y + bzv)));
    }

    // ---- H = tanh([x|rm] @ WhT + bh) ; m = (1-z)*m_prev + z*h ----
    #pragma unroll
    for (int r = 0; r < 16; r++) acc2[r] = 0ULL;
    #pragma unroll 2
    for (int kk = 0; kk < 64; kk++) {
        ulonglong2 w = g_Wh4[kk * NH + j];
        #pragma unroll
        for (int r = 0; r < 16; r++) {
            ulonglong2 a = SX[rbase + r * 64 + kk];
            FFMA2(acc2[r], a.x, w.x);
            FFMA2(acc2[r], a.y, w.y);
        }
    }
    #pragma unroll 2
    for (int kk = 0; kk < 64; kk++) {
        ulonglong2 w = g_Wh4[(64 + kk) * NH + j];
        #pragma unroll
        for (int r = 0; r < 16; r++) {
            ulonglong2 a = SR[rbase + r * 64 + kk];
            FFMA2(acc2[r], a.x, w.x);
            FFMA2(acc2[r], a.y, w.y);
        }
    }
    float marr[16];
    const float bhv = bh[j];
    #pragma unroll
    for (int r = 0; r < 16; r++) {
        float2 t = unpack2(acc2[r]);
        float h = tanhf(t.x + t.y + bhv);
        int rg = rh * 16 + r;
        float m = (1.f - zg[r]) * sm[rg][j] + zg[r] * h;
        marr[r] = m;
        m_out[(row0 + rg) * NH + j] = m;
    }
    __syncthreads();

    // restage: sx <- x_dst, sr <- m
    #pragma unroll
    for (int rl = 0; rl < 16; rl++) {
        int rg = rh * 16 + rl;
        int b = row0 + rg;
        int w = wid[b * NL + td];
        sx[rg][j] = emb[w * NH + j];
        sr[rg][j] = marr[rl];
    }
    __syncthreads();

    // ---- R = sigmoid(x_dst @ WrT + m @ UrT + br) ; rm = r*m ----
    #pragma unroll
    for (int r = 0; r < 16; r++) acc2[r] = 0ULL;
    #pragma unroll 2
    for (int kk = 0; kk < 64; kk++) {
        ulonglong2 w = g_C4[kk * NH + j];
        #pragma unroll
        for (int r = 0; r < 16; r++) {
            ulonglong2 a = SX[rbase + r * 64 + kk];
            FFMA2(acc2[r], a.x, w.x);
            FFMA2(acc2[r], a.y, w.y);
        }
    }
    #pragma unroll 2
    for (int kk = 0; kk < 64; kk++) {
        ulonglong2 w = g_C4[(64 + kk) * NH + j];
        #pragma unroll
        for (int r = 0; r < 16; r++) {
            ulonglong2 a = SR[rbase + r * 64 + kk];
            FFMA2(acc2[r], a.x, w.x);
            FFMA2(acc2[r], a.y, w.y);
        }
    }
    const float brv = br[j];
    #pragma unroll
    for (int r = 0; r < 16; r++) {
        float2 t = unpack2(acc2[r]);
        float rg_ = 1.f / (1.f + expf(-(t.x + t.y + brv)));
        rmbuf[(row0 + rh * 16 + r) * NH + j] = rg_ * marr[r];
    }
}

// ---------------- q path ----------------
__global__ __launch_bounds__(512, 1) void k_q(const int* __restrict__ wid,
                                              const float* __restrict__ tree,
                                              const float* __restrict__ Wb,
                                              const float* __restrict__ Wob) {
    extern __shared__ __align__(16) float smem[];
    float* hid = smem;                 // MT x 256
    float* buf = smem + MT * NH;       // MT x 800 (input phase uses MT x 320)
    __shared__ float s_red[MT];
    __shared__ int s_cnt[MT];
    const int tid = threadIdx.x;
    const int j = tid & 255;
    const int rh = tid >> 8;
    const int row0 = blockIdx.x * MT;
    const int t = row0 / NB;

    for (int r = 0; r < MT; r++) {
        int b = row0 + r - t * NB;
        for (int k = tid; k < NH + NLAT; k += 512) {
            float v;
            if (k < NH) v = (t == 0) ? 0.f : g_mfwd[(t - 1) * NB * NH + b * NH + k];
            else        v = tree[b * NLAT + (k - NH)];
            buf[r * 320 + k] = v;
        }
    }
    __syncthreads();

    const ulonglong2* BUF = (const ulonglong2*)buf;   // row stride 80
    const int rbase80 = rh * 16 * 80;
    unsigned long long acc2[16];
    #pragma unroll
    for (int r = 0; r < 16; r++) acc2[r] = 0ULL;
    #pragma unroll 2
    for (int kk = 0; kk < 80; kk++) {
        ulonglong2 w = g_Wq4[kk * NH + j];
        #pragma unroll
        for (int r = 0; r < 16; r++) {
            ulonglong2 a = BUF[rbase80 + r * 80 + kk];
            FFMA2(acc2[r], a.x, w.x);
            FFMA2(acc2[r], a.y, w.y);
        }
    }
    const float wbv = Wb[j];
    #pragma unroll
    for (int r = 0; r < 16; r++) {
        float2 tt = unpack2(acc2[r]);
        hid[(rh * 16 + r) * NH + j] = fmaxf(tt.x + tt.y + wbv, 0.f);
    }
    __syncthreads();

    const ulonglong2* HID = (const ulonglong2*)hid;   // row stride 64
    const int rbase64 = rh * 16 * 64;
    for (int g = 0; g < 4; g++) {
        int c = g * 256 + j;
        if (c < NV) {
            unsigned long long aq[16];
            #pragma unroll
            for (int r = 0; r < 16; r++) aq[r] = 0ULL;
            #pragma unroll 2
            for (int kk = 0; kk < 64; kk++) {
                ulonglong2 w = g_Wo4[kk * NV + c];
                #pragma unroll
                for (int r = 0; r < 16; r++) {
                    ulonglong2 h = HID[rbase64 + r * 64 + kk];
                    FFMA2(aq[r], h.x, w.x);
                    FFMA2(aq[r], h.y, w.y);
                }
            }
            float wob = Wob[c];
            #pragma unroll
            for (int r = 0; r < 16; r++) {
                float2 tt = unpack2(aq[r]);
                buf[(rh * 16 + r) * NV + c] = tt.x + tt.y + wob;
            }
        }
    }
    __syncthreads();

    const int warp = tid >> 5, lane = tid & 31;   // 16 warps
    for (int rr = 0; rr < 2; rr++) {
        int r = warp + rr * 16;
        float mx = -1e30f; int ai = 0;
        for (int c = lane; c < NV; c += 32) {
            float v = buf[r * NV + c];
            if (v > mx) { mx = v; ai = c; }
        }
        for (int off = 16; off; off >>= 1) {
            float vo = __shfl_xor_sync(0xffffffffu, mx, off);
            int io = __shfl_xor_sync(0xffffffffu, ai, off);
            if (vo > mx || (vo == mx && io < ai)) { mx = vo; ai = io; }
        }
        float sum = 0.f;
        for (int c = lane; c < NV; c += 32) sum += expf(buf[r * NV + c] - mx);
        for (int off = 16; off; off >>= 1) sum += __shfl_xor_sync(0xffffffffu, sum, off);
        if (lane == 0) {
            int b = row0 + r - t * NB;
            int qt = wid[b * NL + t];
            float logZ = mx + logf(sum);
            s_red[r] = logZ - buf[r * NV + qt];
            s_cnt[r] = (ai == qt) ? 1 : 0;
        }
    }
    __syncthreads();
    if (tid == 0) {
        double sum = 0.0; unsigned long long c = 0;
        for (int r = 0; r < MT; r++) { sum += (double)s_red[r]; c += (unsigned long long)s_cnt[r]; }
        atomicAdd(&g_qloss, sum);
        atomicAdd(&g_qcnt, c);
    }
}

// ---------------- p path ----------------
__global__ __launch_bounds__(512, 1) void k_p(const int* __restrict__ wid,
                                              const float* __restrict__ tree,
                                              const float* __restrict__ emb,
                                              const float* __restrict__ Ub,
                                              const float* __restrict__ Usw,
                                              const float* __restrict__ Usb) {
    extern __shared__ __align__(16) float smem[];
    float* a = smem;                  // MT x 576
    float* hid = smem + MT * 576;     // MT x 256
    __shared__ float s_red[MT];
    __shared__ int s_cnt[MT];
    const int tid = threadIdx.x;
    const int j = tid & 255;
    const int rh = tid >> 8;
    const int row0 = blockIdx.x * MT;
    const int s = row0 / NB;
    const int tx = (s == 0) ? 0 : (s <= 15 ? s : 30 - s);

    for (int r = 0; r < MT; r++) {
        int b = row0 + r - s * NB;
        int w = wid[b * NL + tx];
        for (int k = tid; k < 576; k += 512) {
            float v;
            if (k < 256) v = emb[w * NH + k];
            else if (k < 512) {
                int kk = k - 256;
                if (s == 0) v = 0.f;
                else if (s <= 15) v = g_mfwd[(s - 1) * NB * NH + b * NH + kk];
                else {
                    int jj = 30 - s;
                    v = g_mrev[jj * NB * NH + b * NH + kk];
                    if (jj > 0) v += g_mfwd[(jj - 1) * NB * NH + b * NH + kk];
                }
            } else v = tree[b * NLAT + (k - 512)];
            a[r * 576 + k] = v;
        }
    }
    __syncthreads();

    const ulonglong2* A2 = (const ulonglong2*)a;   // row stride 144
    const int rbase144 = rh * 16 * 144;
    unsigned long long acc2[16];
    #pragma unroll
    for (int r = 0; r < 16; r++) acc2[r] = 0ULL;
    #pragma unroll 2
    for (int kk = 0; kk < 144; kk++) {
        ulonglong2 w = g_Up4[kk * NH + j];
        #pragma unroll
        for (int r = 0; r < 16; r++) {
            ulonglong2 av = A2[rbase144 + r * 144 + kk];
            FFMA2(acc2[r], av.x, w.x);
            FFMA2(acc2[r], av.y, w.y);
        }
    }
    const float ubv = Ub[j];
    #pragma unroll
    for (int r = 0; r < 16; r++) {
        float2 tt = unpack2(acc2[r]);
        hid[(rh * 16 + r) * NH + j] = fmaxf(tt.x + tt.y + ubv, 0.f);
    }
    __syncthreads();

    const int warp = tid >> 5, lane = tid & 31;
    const float ptv = (s < 15) ? 1.f : 0.f;
    for (int rr = 0; rr < 2; rr++) {
        int r = warp + rr * 16;
        float ps = 0.f;
        for (int c = lane; c < NH; c += 32) ps += hid[r * NH + c] * Usw[c];
        for (int off = 16; off; off >>= 1) ps += __shfl_xor_sync(0xffffffffu, ps, off);
        if (lane == 0) {
            float p = ps + Usb[0];
            float loss = fmaxf(p, 0.f) + log1pf(expf(-fabsf(p))) - p * ptv;
            s_red[r] = loss;
            s_cnt[r] = ((p > 0.f) == (ptv > 0.5f)) ? 1 : 0;
        }
    }
    __syncthreads();
    if (tid == 0) {
        double sum = 0.0; unsigned long long c = 0;
        for (int r = 0; r < MT; r++) { sum += (double)s_red[r]; c += (unsigned long long)s_cnt[r]; }
        atomicAdd(&g_ploss, sum);
        atomicAdd(&g_pcnt, c);
    }
}

// ---------------- finalize ----------------
__global__ void k_fin(float* __restrict__ out) {
    out[0] = (float)(g_qloss / (double)NB);
    out[1] = (float)(g_ploss / (double)NB);
    out[2] = (float)((double)g_qcnt / (double)(NL * NB));
    out[3] = (float)((double)g_pcnt / (double)((2 * NL - 1) * NB));
}

extern "C" void kernel_launch(void* const* d_in, const int* in_sizes, int n_in,
                              void* d_out, int out_size) {
    const int*   wid  = (const int*)  d_in[0];
    const float* tree = (const float*)d_in[1];
    const float* emb  = (const float*)d_in[2];
    const float* Wz_w = (const float*)d_in[3];
    const float* Wz_b = (const float*)d_in[4];
    const float* Wr_w = (const float*)d_in[5];
    const float* Ur_w = (const float*)d_in[6];
    const float* Ur_b = (const float*)d_in[7];
    const float* Wh_w = (const float*)d_in[8];
    const float* Wh_b = (const float*)d_in[9];
    const float* W_w  = (const float*)d_in[10];
    const float* W_b  = (const float*)d_in[11];
    const float* U_w  = (const float*)d_in[12];
    const float* U_b  = (const float*)d_in[13];
    const float* Wo_w = (const float*)d_in[14];
    const float* Wo_b = (const float*)d_in[15];
    const float* Us_w = (const float*)d_in[16];
    const float* Us_b = (const float*)d_in[17];
    float* out = (float*)d_out;

    const int gru_smem = 3 * MT * NH * 4;                  // 98304 B
    const int q_smem = (MT * NH + MT * NV) * 4;            // 135168 B
    const int p_smem = (MT * 576 + MT * NH) * 4;           // 106496 B
    cudaFuncSetAttribute(k_gru, cudaFuncAttributeMaxDynamicSharedMemorySize, gru_smem);
    cudaFuncSetAttribute(k_q,   cudaFuncAttributeMaxDynamicSharedMemorySize, q_smem);
    cudaFuncSetAttribute(k_p,   cudaFuncAttributeMaxDynamicSharedMemorySize, p_smem);

    k_init<<<1, 32>>>();

    auto tg = [](int n) { return (n + 255) / 256; };
    k_repack<<<tg(256 * 512), 256>>>(Wz_w, 256, 512, 0, 0);
    k_repack<<<tg(256 * 512), 256>>>(Wh_w, 256, 512, 1, 0);
    k_repack<<<tg(256 * 256), 256>>>(Wr_w, 256, 256, 2, 0);
    k_repack<<<tg(256 * 256), 256>>>(Ur_w, 256, 256, 2, 256);
    k_repack<<<tg(256 * 320), 256>>>(W_w,  256, 320, 3, 0);
    k_repack<<<tg(256 * 576), 256>>>(U_w,  256, 576, 4, 0);
    k_repack<<<tg(800 * 256), 256>>>(Wo_w, 800, 256, 5, 0);

    for (int t = 0; t < STEPS; t++)
        k_gru<<<2 * (NB / MT), 512, gru_smem>>>(wid, emb, Wz_b, Wh_b, Ur_b, t);

    k_q<<<(NL * NB) / MT, 512, q_smem>>>(wid, tree, W_b, Wo_b);
    k_p<<<((2 * NL - 1) * NB) / MT, 512, p_smem>>>(wid, tree, emb, U_b, Us_w, Us_b);
    k_fin<<<1, 1>>>(out);
}

// round 8
// speedup vs baseline: 1.1179x; 1.1179x over previous
#include <cuda_runtime.h>
#include <cuda_bf16.h>
#include <math.h>

// Problem constants
static constexpr int NB = 4096;   // batch
static constexpr int NL = 16;     // seq length
static constexpr int NH = 256;    // hidden
static constexpr int NLAT = 64;   // latent
static constexpr int NV = 800;    // vocab
static constexpr int STEPS = NL - 1;  // 15

// ---------------- packed f32x2 helpers ----------------
#define FFMA2(acc, a, b) asm("fma.rn.f32x2 %0, %1, %2, %0;" : "+l"(acc) : "l"(a), "l"(b))

static __device__ __forceinline__ float2 unpack2(unsigned long long v) {
    float2 f;
    asm("mov.b64 {%0, %1}, %2;" : "=f"(f.x), "=f"(f.y) : "l"(v));
    return f;
}

// ---------------- device scratch (allocation-free) ----------------
__device__ float g_mfwd[STEPS * NB * NH];
__device__ float g_mrev[STEPS * NB * NH];
__device__ float g_rm0[NB * NH];            // fwd carry r*m
__device__ float g_rm1[NB * NH];            // rev carry r*m
// pair-interleaved weights: float index ((k>>2)*J + col)*4 + (k&3), as ulonglong2
__device__ ulonglong2 g_Wz4[512 * 256 / 4];
__device__ ulonglong2 g_Wh4[512 * 256 / 4];
__device__ ulonglong2 g_C4 [512 * 256 / 4];   // [Wr ; Ur]
__device__ ulonglong2 g_Wq4[320 * 256 / 4];
__device__ ulonglong2 g_Up4[576 * 256 / 4];
__device__ ulonglong2 g_Wo4[256 * 800 / 4];
__device__ double g_qloss, g_ploss;
__device__ unsigned long long g_qcnt, g_pcnt;

// ---------------- init ----------------
__global__ void k_init() {
    if (threadIdx.x == 0) {
        g_qloss = 0.0; g_ploss = 0.0; g_qcnt = 0ULL; g_pcnt = 0ULL;
    }
}

// ---------------- single-launch repack of all weight matrices ----------------
// seg layout (in elements): Wz 256x512 -> g_Wz4 | Wh 256x512 -> g_Wh4 |
// Wr 256x256 -> g_C4 (koff 0) | Ur 256x256 -> g_C4 (koff 256) |
// W 256x320 -> g_Wq4 | U 256x576 -> g_Up4 | Wo 800x256 -> g_Wo4
__global__ void k_repack_all(const float* __restrict__ Wz, const float* __restrict__ Wh,
                             const float* __restrict__ Wr, const float* __restrict__ Ur,
                             const float* __restrict__ Wq, const float* __restrict__ Up,
                             const float* __restrict__ Wo) {
    int idx = blockIdx.x * blockDim.x + threadIdx.x;
    const float* src; float* dst; int J, K, koff;
    // segment boundaries
    const int n0 = 256 * 512, n1 = n0 + 256 * 512, n2 = n1 + 256 * 256,
              n3 = n2 + 256 * 256, n4 = n3 + 256 * 320, n5 = n4 + 256 * 576,
              n6 = n5 + 800 * 256;
    if (idx >= n6) return;
    if      (idx < n0) { src = Wz; dst = (float*)g_Wz4; J = 256; K = 512; koff = 0; }
    else if (idx < n1) { src = Wh; dst = (float*)g_Wh4; J = 256; K = 512; koff = 0; idx -= n0; }
    else if (idx < n2) { src = Wr; dst = (float*)g_C4;  J = 256; K = 256; koff = 0; idx -= n1; }
    else if (idx < n3) { src = Ur; dst = (float*)g_C4;  J = 256; K = 256; koff = 256; idx -= n2; }
    else if (idx < n4) { src = Wq; dst = (float*)g_Wq4; J = 256; K = 320; koff = 0; idx -= n3; }
    else if (idx < n5) { src = Up; dst = (float*)g_Up4; J = 256; K = 576; koff = 0; idx -= n4; }
    else               { src = Wo; dst = (float*)g_Wo4; J = 800; K = 256; koff = 0; idx -= n5; }
    int jcol = idx / K, k = idx % K;
    int kk = k + koff;
    dst[((kk >> 2) * J + jcol) * 4 + (kk & 3)] = src[jcol * K + k];
}

// ---------------- fused fwd+rev GRU step (R5 inner loops, 256 thr, 2 CTA/SM) ----------------
// blockIdx < 256: fwd chain; blockIdx >= 256: rev chain (independent)
__global__ __launch_bounds__(256, 2) void k_gru(const int* __restrict__ wid,
                                                const float* __restrict__ emb,
                                                const float* __restrict__ bz,
                                                const float* __restrict__ bh,
                                                const float* __restrict__ br,
                                                int step) {
    __shared__ __align__(16) float sx[16][NH];
    __shared__ __align__(16) float sm[16][NH];
    __shared__ __align__(16) float sr[16][NH];
    const int j = threadIdx.x;
    const int dir = blockIdx.x >> 8;
    const int row0 = (blockIdx.x & 255) * 16;

    int ts, td;
    const float* m_prev;
    float* m_out;
    float* rmbuf;
    if (dir == 0) {
        ts = step; td = step + 1;
        m_prev = (step == 0) ? nullptr : &g_mfwd[(step - 1) * NB * NH];
        m_out = &g_mfwd[step * NB * NH];
        rmbuf = g_rm0;
    } else {
        ts = 15 - step; td = 14 - step;
        m_prev = (step == 0) ? nullptr : &g_mrev[(15 - step) * NB * NH];
        m_out = &g_mrev[(14 - step) * NB * NH];
        rmbuf = g_rm1;
    }

    #pragma unroll
    for (int r = 0; r < 16; r++) {
        int b = row0 + r;
        int w = wid[b * NL + ts];
        sx[r][j] = emb[w * NH + j];
        if (m_prev) { sm[r][j] = m_prev[b * NH + j]; sr[r][j] = rmbuf[b * NH + j]; }
        else        { sm[r][j] = 0.f;                sr[r][j] = 0.f; }
    }
    __syncthreads();

    const ulonglong2* SX = (const ulonglong2*)sx;   // [r*64 + kk]
    const ulonglong2* SM = (const ulonglong2*)sm;
    const ulonglong2* SR = (const ulonglong2*)sr;

    // ---- Z = sigmoid([x|m] @ WzT + bz) ----
    unsigned long long acc2[16];
    #pragma unroll
    for (int r = 0; r < 16; r++) acc2[r] = 0ULL;
    #pragma unroll 2
    for (int kk = 0; kk < 64; kk++) {
        ulonglong2 w = g_Wz4[kk * NH + j];
        #pragma unroll
        for (int r = 0; r < 16; r++) {
            ulonglong2 a = SX[r * 64 + kk];
            FFMA2(acc2[r], a.x, w.x);
            FFMA2(acc2[r], a.y, w.y);
        }
    }
    #pragma unroll 2
    for (int kk = 0; kk < 64; kk++) {
        ulonglong2 w = g_Wz4[(64 + kk) * NH + j];
        #pragma unroll
        for (int r = 0; r < 16; r++) {
            ulonglong2 a = SM[r * 64 + kk];
            FFMA2(acc2[r], a.x, w.x);
            FFMA2(acc2[r], a.y, w.y);
        }
    }
    float zg[16];
    const float bzv = bz[j];
    #pragma unroll
    for (int r = 0; r < 16; r++) {
        float2 t = unpack2(acc2[r]);
        zg[r] = 1.f / (1.f + expf(-(t.x + t.y + bzv)));
    }

    // ---- H = tanh([x|rm] @ WhT + bh) ; m = (1-z)*m_prev + z*h ----
    #pragma unroll
    for (int r = 0; r < 16; r++) acc2[r] = 0ULL;
    #pragma unroll 2
    for (int kk = 0; kk < 64; kk++) {
        ulonglong2 w = g_Wh4[kk * NH + j];
        #pragma unroll
        for (int r = 0; r < 16; r++) {
            ulonglong2 a = SX[r * 64 + kk];
            FFMA2(acc2[r], a.x, w.x);
            FFMA2(acc2[r], a.y, w.y);
        }
    }
    #pragma unroll 2
    for (int kk = 0; kk < 64; kk++) {
        ulonglong2 w = g_Wh4[(64 + kk) * NH + j];
        #pragma unroll
        for (int r = 0; r < 16; r++) {
            ulonglong2 a = SR[r * 64 + kk];
            FFMA2(acc2[r], a.x, w.x);
            FFMA2(acc2[r], a.y, w.y);
        }
    }
    float marr[16];
    const float bhv = bh[j];
    #pragma unroll
    for (int r = 0; r < 16; r++) {
        float2 t = unpack2(acc2[r]);
        float h = tanhf(t.x + t.y + bhv);
        float m = (1.f - zg[r]) * sm[r][j] + zg[r] * h;
        marr[r] = m;
        m_out[(row0 + r) * NH + j] = m;
    }
    __syncthreads();

    // restage: sx <- x_dst, sr <- m
    #pragma unroll
    for (int r = 0; r < 16; r++) {
        int b = row0 + r;
        int w = wid[b * NL + td];
        sx[r][j] = emb[w * NH + j];
        sr[r][j] = marr[r];
    }
    __syncthreads();

    // ---- R = sigmoid(x_dst @ WrT + m @ UrT + br) ; rm = r*m ----
    #pragma unroll
    for (int r = 0; r < 16; r++) acc2[r] = 0ULL;
    #pragma unroll 2
    for (int kk = 0; kk < 64; kk++) {
        ulonglong2 w = g_C4[kk * NH + j];
        #pragma unroll
        for (int r = 0; r < 16; r++) {
            ulonglong2 a = SX[r * 64 + kk];
            FFMA2(acc2[r], a.x, w.x);
            FFMA2(acc2[r], a.y, w.y);
        }
    }
    #pragma unroll 2
    for (int kk = 0; kk < 64; kk++) {
        ulonglong2 w = g_C4[(64 + kk) * NH + j];
        #pragma unroll
        for (int r = 0; r < 16; r++) {
            ulonglong2 a = SR[r * 64 + kk];
            FFMA2(acc2[r], a.x, w.x);
            FFMA2(acc2[r], a.y, w.y);
        }
    }
    const float brv = br[j];
    #pragma unroll
    for (int r = 0; r < 16; r++) {
        float2 t = unpack2(acc2[r]);
        float rg = 1.f / (1.f + expf(-(t.x + t.y + brv)));
        rmbuf[(row0 + r) * NH + j] = rg * marr[r];
    }
}

// ---------------- q path ----------------
__global__ __launch_bounds__(256, 2) void k_q(const int* __restrict__ wid,
                                              const float* __restrict__ tree,
                                              const float* __restrict__ Wb,
                                              const float* __restrict__ Wob) {
    extern __shared__ __align__(16) float smem[];
    float* hid = smem;                 // 16 x 256
    float* buf = smem + 16 * NH;       // 16 x 800 (input phase uses 16 x 320)
    __shared__ float s_red[16];
    __shared__ int s_cnt[16];
    const int j = threadIdx.x;
    const int row0 = blockIdx.x * 16;
    const int t = row0 / NB;

    for (int r = 0; r < 16; r++) {
        int b = row0 + r - t * NB;
        for (int k = j; k < NH + NLAT; k += 256) {
            float v;
            if (k < NH) v = (t == 0) ? 0.f : g_mfwd[(t - 1) * NB * NH + b * NH + k];
            else        v = tree[b * NLAT + (k - NH)];
            buf[r * 320 + k] = v;
        }
    }
    __syncthreads();

    const ulonglong2* BUF = (const ulonglong2*)buf;   // row stride 80
    unsigned long long acc2[16];
    #pragma unroll
    for (int r = 0; r < 16; r++) acc2[r] = 0ULL;
    #pragma unroll 2
    for (int kk = 0; kk < 80; kk++) {
        ulonglong2 w = g_Wq4[kk * NH + j];
        #pragma unroll
        for (int r = 0; r < 16; r++) {
            ulonglong2 a = BUF[r * 80 + kk];
            FFMA2(acc2[r], a.x, w.x);
            FFMA2(acc2[r], a.y, w.y);
        }
    }
    const float wbv = Wb[j];
    #pragma unroll
    for (int r = 0; r < 16; r++) {
        float2 tt = unpack2(acc2[r]);
        hid[r * NH + j] = fmaxf(tt.x + tt.y + wbv, 0.f);
    }
    __syncthreads();

    const ulonglong2* HID = (const ulonglong2*)hid;   // row stride 64
    for (int g = 0; g < 4; g++) {
        int c = g * 256 + j;
        if (c < NV) {
            unsigned long long aq[16];
            #pragma unroll
            for (int r = 0; r < 16; r++) aq[r] = 0ULL;
            #pragma unroll 2
            for (int kk = 0; kk < 64; kk++) {
                ulonglong2 w = g_Wo4[kk * NV + c];
                #pragma unroll
                for (int r = 0; r < 16; r++) {
                    ulonglong2 h = HID[r * 64 + kk];
                    FFMA2(aq[r], h.x, w.x);
                    FFMA2(aq[r], h.y, w.y);
                }
            }
            float wob = Wob[c];
            #pragma unroll
            for (int r = 0; r < 16; r++) {
                float2 tt = unpack2(aq[r]);
                buf[r * NV + c] = tt.x + tt.y + wob;
            }
        }
    }
    __syncthreads();

    const int warp = j >> 5, lane = j & 31;
    for (int rr = 0; rr < 2; rr++) {
        int r = warp + rr * 8;
        float mx = -1e30f; int ai = 0;
        for (int c = lane; c < NV; c += 32) {
            float v = buf[r * NV + c];
            if (v > mx) { mx = v; ai = c; }
        }
        for (int off = 16; off; off >>= 1) {
            float vo = __shfl_xor_sync(0xffffffffu, mx, off);
            int io = __shfl_xor_sync(0xffffffffu, ai, off);
            if (vo > mx || (vo == mx && io < ai)) { mx = vo; ai = io; }
        }
        float sum = 0.f;
        for (int c = lane; c < NV; c += 32) sum += expf(buf[r * NV + c] - mx);
        for (int off = 16; off; off >>= 1) sum += __shfl_xor_sync(0xffffffffu, sum, off);
        if (lane == 0) {
            int b = row0 + r - t * NB;
            int qt = wid[b * NL + t];
            float logZ = mx + logf(sum);
            s_red[r] = logZ - buf[r * NV + qt];
            s_cnt[r] = (ai == qt) ? 1 : 0;
        }
    }
    __syncthreads();
    if (j == 0) {
        double sum = 0.0; unsigned long long c = 0;
        for (int r = 0; r < 16; r++) { sum += (double)s_red[r]; c += (unsigned long long)s_cnt[r]; }
        atomicAdd(&g_qloss, sum);
        atomicAdd(&g_qcnt, c);
    }
}

// ---------------- p path ----------------
__global__ __launch_bounds__(256, 2) void k_p(const int* __restrict__ wid,
                                              const float* __restrict__ tree,
                                              const float* __restrict__ emb,
                                              const float* __restrict__ Ub,
                                              const float* __restrict__ Usw,
                                              const float* __restrict__ Usb) {
    extern __shared__ __align__(16) float smem[];
    float* a = smem;                 // 16 x 576
    float* hid = smem + 16 * 576;    // 16 x 256
    __shared__ float s_red[16];
    __shared__ int s_cnt[16];
    const int j = threadIdx.x;
    const int row0 = blockIdx.x * 16;
    const int s = row0 / NB;
    const int tx = (s == 0) ? 0 : (s <= 15 ? s : 30 - s);

    for (int r = 0; r < 16; r++) {
        int b = row0 + r - s * NB;
        int w = wid[b * NL + tx];
        for (int k = j; k < 576; k += 256) {
            float v;
            if (k < 256) v = emb[w * NH + k];
            else if (k < 512) {
                int kk = k - 256;
                if (s == 0) v = 0.f;
                else if (s <= 15) v = g_mfwd[(s - 1) * NB * NH + b * NH + kk];
                else {
                    int jj = 30 - s;
                    v = g_mrev[jj * NB * NH + b * NH + kk];
                    if (jj > 0) v += g_mfwd[(jj - 1) * NB * NH + b * NH + kk];
                }
            } else v = tree[b * NLAT + (k - 512)];
            a[r * 576 + k] = v;
        }
    }
    __syncthreads();

    const ulonglong2* A2 = (const ulonglong2*)a;   // row stride 144
    unsigned long long acc2[16];
    #pragma unroll
    for (int r = 0; r < 16; r++) acc2[r] = 0ULL;
    #pragma unroll 2
    for (int kk = 0; kk < 144; kk++) {
        ulonglong2 w = g_Up4[kk * NH + j];
        #pragma unroll
        for (int r = 0; r < 16; r++) {
            ulonglong2 av = A2[r * 144 + kk];
            FFMA2(acc2[r], av.x, w.x);
            FFMA2(acc2[r], av.y, w.y);
        }
    }
    const float ubv = Ub[j];
    #pragma unroll
    for (int r = 0; r < 16; r++) {
        float2 tt = unpack2(acc2[r]);
        hid[r * NH + j] = fmaxf(tt.x + tt.y + ubv, 0.f);
    }
    __syncthreads();

    const int warp = j >> 5, lane = j & 31;
    const float ptv = (s < 15) ? 1.f : 0.f;
    for (int rr = 0; rr < 2; rr++) {
        int r = warp + rr * 8;
        float ps = 0.f;
        for (int c = lane; c < NH; c += 32) ps += hid[r * NH + c] * Usw[c];
        for (int off = 16; off; off >>= 1) ps += __shfl_xor_sync(0xffffffffu, ps, off);
        if (lane == 0) {
            float p = ps + Usb[0];
            float loss = fmaxf(p, 0.f) + log1pf(expf(-fabsf(p))) - p * ptv;
            s_red[r] = loss;
            s_cnt[r] = ((p > 0.f) == (ptv > 0.5f)) ? 1 : 0;
        }
    }
    __syncthreads();
    if (j == 0) {
        double sum = 0.0; unsigned long long c = 0;
        for (int r = 0; r < 16; r++) { sum += (double)s_red[r]; c += (unsigned long long)s_cnt[r]; }
        atomicAdd(&g_ploss, sum);
        atomicAdd(&g_pcnt, c);
    }
}

// ---------------- finalize ----------------
__global__ void k_fin(float* __restrict__ out) {
    out[0] = (float)(g_qloss / (double)NB);
    out[1] = (float)(g_ploss / (double)NB);
    out[2] = (float)((double)g_qcnt / (double)(NL * NB));
    out[3] = (float)((double)g_pcnt / (double)((2 * NL - 1) * NB));
}

extern "C" void kernel_launch(void* const* d_in, const int* in_sizes, int n_in,
                              void* d_out, int out_size) {
    const int*   wid  = (const int*)  d_in[0];
    const float* tree = (const float*)d_in[1];
    const float* emb  = (const float*)d_in[2];
    const float* Wz_w = (const float*)d_in[3];
    const float* Wz_b = (const float*)d_in[4];
    const float* Wr_w = (const float*)d_in[5];
    const float* Ur_w = (const float*)d_in[6];
    const float* Ur_b = (const float*)d_in[7];
    const float* Wh_w = (const float*)d_in[8];
    const float* Wh_b = (const float*)d_in[9];
    const float* W_w  = (const float*)d_in[10];
    const float* W_b  = (const float*)d_in[11];
    const float* U_w  = (const float*)d_in[12];
    const float* U_b  = (const float*)d_in[13];
    const float* Wo_w = (const float*)d_in[14];
    const float* Wo_b = (const float*)d_in[15];
    const float* Us_w = (const float*)d_in[16];
    const float* Us_b = (const float*)d_in[17];
    float* out = (float*)d_out;

    const int q_smem = (16 * NH + 16 * NV) * 4;        // 67584 B
    const int p_smem = (16 * 576 + 16 * NH) * 4;       // 53248 B
    cudaFuncSetAttribute(k_q, cudaFuncAttributeMaxDynamicSharedMemorySize, q_smem);
    cudaFuncSetAttribute(k_p, cudaFuncAttributeMaxDynamicSharedMemorySize, p_smem);

    k_init<<<1, 32>>>();

    const int total = 256 * 512 * 2 + 256 * 256 * 2 + 256 * 320 + 256 * 576 + 800 * 256;
    k_repack_all<<<(total + 255) / 256, 256>>>(Wz_w, Wh_w, Wr_w, Ur_w, W_w, U_w, Wo_w);

    for (int t = 0; t < STEPS; t++)
        k_gru<<<512, 256>>>(wid, emb, Wz_b, Wh_b, Ur_b, t);

    k_q<<<(NL * NB) / 16, 256, q_smem>>>(wid, tree, W_b, Wo_b);
    k_p<<<((2 * NL - 1) * NB) / 16, 256, p_smem>>>(wid, tree, emb, U_b, Us_w, Us_b);
    k_fin<<<1, 1>>>(out);
}

// round 9
// speedup vs baseline: 1.2603x; 1.1274x over previous
#include <cuda_runtime.h>
#include <cuda_bf16.h>
#include <math.h>

// Problem constants
static constexpr int NB = 4096;   // batch
static constexpr int NL = 16;     // seq length
static constexpr int NH = 256;    // hidden
static constexpr int NLAT = 64;   // latent
static constexpr int NV = 800;    // vocab
static constexpr int NVP = 1024;  // padded vocab (for clean 256-col chunks)
static constexpr int STEPS = NL - 1;  // 15

// ---------------- packed f32x2 helpers ----------------
#define FFMA2(acc, a, b) asm("fma.rn.f32x2 %0, %1, %2, %0;" : "+l"(acc) : "l"(a), "l"(b))

static __device__ __forceinline__ float2 unpack2(unsigned long long v) {
    float2 f;
    asm("mov.b64 {%0, %1}, %2;" : "=f"(f.x), "=f"(f.y) : "l"(v));
    return f;
}

// ---------------- device scratch (allocation-free) ----------------
__device__ float g_mfwd[STEPS * NB * NH];
__device__ float g_mrev[STEPS * NB * NH];
__device__ float g_rm0[NB * NH];            // fwd carry r*m
__device__ float g_rm1[NB * NH];            // rev carry r*m
// pair-interleaved weights: float index ((k>>2)*J + col)*4 + (k&3), as ulonglong2
__device__ ulonglong2 g_Wz4[512 * 256 / 4];
__device__ ulonglong2 g_Wh4[512 * 256 / 4];
__device__ ulonglong2 g_C4 [512 * 256 / 4];   // [Wr ; Ur]
__device__ ulonglong2 g_Wq4[320 * 256 / 4];
__device__ ulonglong2 g_Up4[576 * 256 / 4];
__device__ ulonglong2 g_Wo4[256 * NVP / 4];   // padded to 1024 cols (zeros beyond 800)
__device__ double g_qloss, g_ploss;
__device__ unsigned long long g_qcnt, g_pcnt;

// ---------------- init ----------------
__global__ void k_init() {
    if (threadIdx.x == 0) {
        g_qloss = 0.0; g_ploss = 0.0; g_qcnt = 0ULL; g_pcnt = 0ULL;
    }
}

// ---------------- single-launch repack of all weight matrices ----------------
__global__ void k_repack_all(const float* __restrict__ Wz, const float* __restrict__ Wh,
                             const float* __restrict__ Wr, const float* __restrict__ Ur,
                             const float* __restrict__ Wq, const float* __restrict__ Up,
                             const float* __restrict__ Wo) {
    int idx = blockIdx.x * blockDim.x + threadIdx.x;
    const int n0 = 256 * 512, n1 = n0 + 256 * 512, n2 = n1 + 256 * 256,
              n3 = n2 + 256 * 256, n4 = n3 + 256 * 320, n5 = n4 + 256 * 576,
              n6 = n5 + NVP * 256;
    if (idx >= n6) return;
    if (idx >= n5) {
        // Wo: J=1024 padded cols, K=256; zero-fill beyond 800
        idx -= n5;
        int jcol = idx / 256, k = idx % 256;
        ((float*)g_Wo4)[((k >> 2) * NVP + jcol) * 4 + (k & 3)] =
            (jcol < NV) ? Wo[jcol * 256 + k] : 0.f;
        return;
    }
    const float* src; float* dst; int J, K, koff;
    if      (idx < n0) { src = Wz; dst = (float*)g_Wz4; J = 256; K = 512; koff = 0; }
    else if (idx < n1) { src = Wh; dst = (float*)g_Wh4; J = 256; K = 512; koff = 0; idx -= n0; }
    else if (idx < n2) { src = Wr; dst = (float*)g_C4;  J = 256; K = 256; koff = 0; idx -= n1; }
    else if (idx < n3) { src = Ur; dst = (float*)g_C4;  J = 256; K = 256; koff = 256; idx -= n2; }
    else if (idx < n4) { src = Wq; dst = (float*)g_Wq4; J = 256; K = 320; koff = 0; idx -= n3; }
    else               { src = Up; dst = (float*)g_Up4; J = 256; K = 576; koff = 0; idx -= n4; }
    int jcol = idx / K, k = idx % K;
    int kk = k + koff;
    dst[((kk >> 2) * J + jcol) * 4 + (kk & 3)] = src[jcol * K + k];
}

// ---------------- fused fwd+rev GRU step, 8row x 2col blocking ----------------
// blockIdx < 256: fwd chain; blockIdx >= 256: rev chain (independent)
__global__ __launch_bounds__(256, 2) void k_gru(const int* __restrict__ wid,
                                                const float* __restrict__ emb,
                                                const float* __restrict__ bz,
                                                const float* __restrict__ bh,
                                                const float* __restrict__ br,
                                                int step) {
    __shared__ __align__(16) float sx[16][NH];
    __shared__ __align__(16) float sm[16][NH];
    __shared__ __align__(16) float sr[16][NH];
    const int j = threadIdx.x;          // staging column
    const int c2 = j & 127;             // compute: first col
    const int rg8 = (j >> 7) * 8;       // compute: row base (0 or 8)
    const int dir = blockIdx.x >> 8;
    const int row0 = (blockIdx.x & 255) * 16;

    int ts, td;
    const float* m_prev;
    float* m_out;
    float* rmbuf;
    if (dir == 0) {
        ts = step; td = step + 1;
        m_prev = (step == 0) ? nullptr : &g_mfwd[(step - 1) * NB * NH];
        m_out = &g_mfwd[step * NB * NH];
        rmbuf = g_rm0;
    } else {
        ts = 15 - step; td = 14 - step;
        m_prev = (step == 0) ? nullptr : &g_mrev[(15 - step) * NB * NH];
        m_out = &g_mrev[(14 - step) * NB * NH];
        rmbuf = g_rm1;
    }

    #pragma unroll
    for (int r = 0; r < 16; r++) {
        int b = row0 + r;
        int w = wid[b * NL + ts];
        sx[r][j] = emb[w * NH + j];
        if (m_prev) { sm[r][j] = m_prev[b * NH + j]; sr[r][j] = rmbuf[b * NH + j]; }
        else        { sm[r][j] = 0.f;                sr[r][j] = 0.f; }
    }
    __syncthreads();

    const ulonglong2* SX = (const ulonglong2*)sx;   // [row*64 + kk]
    const ulonglong2* SM = (const ulonglong2*)sm;
    const ulonglong2* SR = (const ulonglong2*)sr;

    // ---- Z = sigmoid([x|m] @ WzT + bz) ----  acc[c*8+r]
    unsigned long long acc[16];
    #pragma unroll
    for (int i = 0; i < 16; i++) acc[i] = 0ULL;
    #pragma unroll 2
    for (int kk = 0; kk < 64; kk++) {
        ulonglong2 w0 = g_Wz4[kk * NH + c2];
        ulonglong2 w1 = g_Wz4[kk * NH + c2 + 128];
        #pragma unroll
        for (int r = 0; r < 8; r++) {
            ulonglong2 a = SX[(rg8 + r) * 64 + kk];
            FFMA2(acc[r], a.x, w0.x);     FFMA2(acc[r], a.y, w0.y);
            FFMA2(acc[8 + r], a.x, w1.x); FFMA2(acc[8 + r], a.y, w1.y);
        }
    }
    #pragma unroll 2
    for (int kk = 0; kk < 64; kk++) {
        ulonglong2 w0 = g_Wz4[(64 + kk) * NH + c2];
        ulonglong2 w1 = g_Wz4[(64 + kk) * NH + c2 + 128];
        #pragma unroll
        for (int r = 0; r < 8; r++) {
            ulonglong2 a = SM[(rg8 + r) * 64 + kk];
            FFMA2(acc[r], a.x, w0.x);     FFMA2(acc[r], a.y, w0.y);
            FFMA2(acc[8 + r], a.x, w1.x); FFMA2(acc[8 + r], a.y, w1.y);
        }
    }
    float zg[16];
    {
        const float b0 = bz[c2], b1 = bz[c2 + 128];
        #pragma unroll
        for (int r = 0; r < 8; r++) {
            float2 t0 = unpack2(acc[r]);
            float2 t1 = unpack2(acc[8 + r]);
            zg[r]     = 1.f / (1.f + expf(-(t0.x + t0.y + b0)));
            zg[8 + r] = 1.f / (1.f + expf(-(t1.x + t1.y + b1)));
        }
    }

    // ---- H = tanh([x|rm] @ WhT + bh) ; m = (1-z)*m_prev + z*h ----
    #pragma unroll
    for (int i = 0; i < 16; i++) acc[i] = 0ULL;
    #pragma unroll 2
    for (int kk = 0; kk < 64; kk++) {
        ulonglong2 w0 = g_Wh4[kk * NH + c2];
        ulonglong2 w1 = g_Wh4[kk * NH + c2 + 128];
        #pragma unroll
        for (int r = 0; r < 8; r++) {
            ulonglong2 a = SX[(rg8 + r) * 64 + kk];
            FFMA2(acc[r], a.x, w0.x);     FFMA2(acc[r], a.y, w0.y);
            FFMA2(acc[8 + r], a.x, w1.x); FFMA2(acc[8 + r], a.y, w1.y);
        }
    }
    #pragma unroll 2
    for (int kk = 0; kk < 64; kk++) {
        ulonglong2 w0 = g_Wh4[(64 + kk) * NH + c2];
        ulonglong2 w1 = g_Wh4[(64 + kk) * NH + c2 + 128];
        #pragma unroll
        for (int r = 0; r < 8; r++) {
            ulonglong2 a = SR[(rg8 + r) * 64 + kk];
            FFMA2(acc[r], a.x, w0.x);     FFMA2(acc[r], a.y, w0.y);
            FFMA2(acc[8 + r], a.x, w1.x); FFMA2(acc[8 + r], a.y, w1.y);
        }
    }
    float marr[16];
    {
        const float b0 = bh[c2], b1 = bh[c2 + 128];
        #pragma unroll
        for (int r = 0; r < 8; r++) {
            float2 t0 = unpack2(acc[r]);
            float2 t1 = unpack2(acc[8 + r]);
            float h0 = tanhf(t0.x + t0.y + b0);
            float h1 = tanhf(t1.x + t1.y + b1);
            float m0 = (1.f - zg[r])     * sm[rg8 + r][c2]       + zg[r] * h0;
            float m1 = (1.f - zg[8 + r]) * sm[rg8 + r][c2 + 128] + zg[8 + r] * h1;
            marr[r] = m0; marr[8 + r] = m1;
            m_out[(row0 + rg8 + r) * NH + c2] = m0;
            m_out[(row0 + rg8 + r) * NH + c2 + 128] = m1;
        }
    }
    __syncthreads();

    // restage: sx <- x_dst (stage by column j), sr <- m (each thread owns its 16)
    #pragma unroll
    for (int r = 0; r < 16; r++) {
        int b = row0 + r;
        int w = wid[b * NL + td];
        sx[r][j] = emb[w * NH + j];
    }
    #pragma unroll
    for (int r = 0; r < 8; r++) {
        sr[rg8 + r][c2] = marr[r];
        sr[rg8 + r][c2 + 128] = marr[8 + r];
    }
    __syncthreads();

    // ---- R = sigmoid(x_dst @ WrT + m @ UrT + br) ; rm = r*m ----
    #pragma unroll
    for (int i = 0; i < 16; i++) acc[i] = 0ULL;
    #pragma unroll 2
    for (int kk = 0; kk < 64; kk++) {
        ulonglong2 w0 = g_C4[kk * NH + c2];
        ulonglong2 w1 = g_C4[kk * NH + c2 + 128];
        #pragma unroll
        for (int r = 0; r < 8; r++) {
            ulonglong2 a = SX[(rg8 + r) * 64 + kk];
            FFMA2(acc[r], a.x, w0.x);     FFMA2(acc[r], a.y, w0.y);
            FFMA2(acc[8 + r], a.x, w1.x); FFMA2(acc[8 + r], a.y, w1.y);
        }
    }
    #pragma unroll 2
    for (int kk = 0; kk < 64; kk++) {
        ulonglong2 w0 = g_C4[(64 + kk) * NH + c2];
        ulonglong2 w1 = g_C4[(64 + kk) * NH + c2 + 128];
        #pragma unroll
        for (int r = 0; r < 8; r++) {
            ulonglong2 a = SR[(rg8 + r) * 64 + kk];
            FFMA2(acc[r], a.x, w0.x);     FFMA2(acc[r], a.y, w0.y);
            FFMA2(acc[8 + r], a.x, w1.x); FFMA2(acc[8 + r], a.y, w1.y);
        }
    }
    {
        const float b0 = br[c2], b1 = br[c2 + 128];
        #pragma unroll
        for (int r = 0; r < 8; r++) {
            float2 t0 = unpack2(acc[r]);
            float2 t1 = unpack2(acc[8 + r]);
            float r0 = 1.f / (1.f + expf(-(t0.x + t0.y + b0)));
            float r1 = 1.f / (1.f + expf(-(t1.x + t1.y + b1)));
            rmbuf[(row0 + rg8 + r) * NH + c2] = r0 * marr[r];
            rmbuf[(row0 + rg8 + r) * NH + c2 + 128] = r1 * marr[8 + r];
        }
    }
}

// ---------------- q path ----------------
__global__ __launch_bounds__(256, 2) void k_q(const int* __restrict__ wid,
                                              const float* __restrict__ tree,
                                              const float* __restrict__ Wb,
                                              const float* __restrict__ Wob) {
    extern __shared__ __align__(16) float smem[];
    float* hid = smem;                 // 16 x 256
    float* buf = smem + 16 * NH;       // 16 x 1024 logits (input phase uses 16 x 320)
    __shared__ float s_red[16];
    __shared__ int s_cnt[16];
    const int j = threadIdx.x;
    const int c2 = j & 127;
    const int rg8 = (j >> 7) * 8;
    const int row0 = blockIdx.x * 16;
    const int t = row0 / NB;

    for (int r = 0; r < 16; r++) {
        int b = row0 + r - t * NB;
        for (int k = j; k < NH + NLAT; k += 256) {
            float v;
            if (k < NH) v = (t == 0) ? 0.f : g_mfwd[(t - 1) * NB * NH + b * NH + k];
            else        v = tree[b * NLAT + (k - NH)];
            buf[r * 320 + k] = v;
        }
    }
    __syncthreads();

    const ulonglong2* BUF = (const ulonglong2*)buf;   // row stride 80
    unsigned long long acc[16];
    #pragma unroll
    for (int i = 0; i < 16; i++) acc[i] = 0ULL;
    #pragma unroll 2
    for (int kk = 0; kk < 80; kk++) {
        ulonglong2 w0 = g_Wq4[kk * NH + c2];
        ulonglong2 w1 = g_Wq4[kk * NH + c2 + 128];
        #pragma unroll
        for (int r = 0; r < 8; r++) {
            ulonglong2 a = BUF[(rg8 + r) * 80 + kk];
            FFMA2(acc[r], a.x, w0.x);     FFMA2(acc[r], a.y, w0.y);
            FFMA2(acc[8 + r], a.x, w1.x); FFMA2(acc[8 + r], a.y, w1.y);
        }
    }
    {
        const float b0 = Wb[c2], b1 = Wb[c2 + 128];
        #pragma unroll
        for (int r = 0; r < 8; r++) {
            float2 t0 = unpack2(acc[r]);
            float2 t1 = unpack2(acc[8 + r]);
            hid[(rg8 + r) * NH + c2]       = fmaxf(t0.x + t0.y + b0, 0.f);
            hid[(rg8 + r) * NH + c2 + 128] = fmaxf(t1.x + t1.y + b1, 0.f);
        }
    }
    __syncthreads();

    const ulonglong2* HID = (const ulonglong2*)hid;   // row stride 64
    for (int g = 0; g < 4; g++) {
        int cA = g * 256 + c2;
        int cB = cA + 128;
        unsigned long long aq[16];
        #pragma unroll
        for (int i = 0; i < 16; i++) aq[i] = 0ULL;
        #pragma unroll 2
        for (int kk = 0; kk < 64; kk++) {
            ulonglong2 w0 = g_Wo4[kk * NVP + cA];
            ulonglong2 w1 = g_Wo4[kk * NVP + cB];
            #pragma unroll
            for (int r = 0; r < 8; r++) {
                ulonglong2 h = HID[(rg8 + r) * 64 + kk];
                FFMA2(aq[r], h.x, w0.x);     FFMA2(aq[r], h.y, w0.y);
                FFMA2(aq[8 + r], h.x, w1.x); FFMA2(aq[8 + r], h.y, w1.y);
            }
        }
        float wobA = (cA < NV) ? Wob[cA] : 0.f;
        float wobB = (cB < NV) ? Wob[cB] : 0.f;
        #pragma unroll
        for (int r = 0; r < 8; r++) {
            float2 t0 = unpack2(aq[r]);
            float2 t1 = unpack2(aq[8 + r]);
            buf[(rg8 + r) * NVP + cA] = t0.x + t0.y + wobA;
            buf[(rg8 + r) * NVP + cB] = t1.x + t1.y + wobB;
        }
    }
    __syncthreads();

    const int warp = j >> 5, lane = j & 31;
    for (int rr = 0; rr < 2; rr++) {
        int r = warp + rr * 8;
        float mx = -1e30f; int ai = 0;
        for (int c = lane; c < NV; c += 32) {
            float v = buf[r * NVP + c];
            if (v > mx) { mx = v; ai = c; }
        }
        for (int off = 16; off; off >>= 1) {
            float vo = __shfl_xor_sync(0xffffffffu, mx, off);
            int io = __shfl_xor_sync(0xffffffffu, ai, off);
            if (vo > mx || (vo == mx && io < ai)) { mx = vo; ai = io; }
        }
        float sum = 0.f;
        for (int c = lane; c < NV; c += 32) sum += expf(buf[r * NVP + c] - mx);
        for (int off = 16; off; off >>= 1) sum += __shfl_xor_sync(0xffffffffu, sum, off);
        if (lane == 0) {
            int b = row0 + r - t * NB;
            int qt = wid[b * NL + t];
            float logZ = mx + logf(sum);
            s_red[r] = logZ - buf[r * NVP + qt];
            s_cnt[r] = (ai == qt) ? 1 : 0;
        }
    }
    __syncthreads();
    if (j == 0) {
        double sum = 0.0; unsigned long long c = 0;
        for (int r = 0; r < 16; r++) { sum += (double)s_red[r]; c += (unsigned long long)s_cnt[r]; }
        atomicAdd(&g_qloss, sum);
        atomicAdd(&g_qcnt, c);
    }
}

// ---------------- p path ----------------
__global__ __launch_bounds__(256, 2) void k_p(const int* __restrict__ wid,
                                              const float* __restrict__ tree,
                                              const float* __restrict__ emb,
                                              const float* __restrict__ Ub,
                                              const float* __restrict__ Usw,
                                              const float* __restrict__ Usb) {
    extern __shared__ __align__(16) float smem[];
    float* a = smem;                 // 16 x 576
    float* hid = smem + 16 * 576;    // 16 x 256
    __shared__ float s_red[16];
    __shared__ int s_cnt[16];
    const int j = threadIdx.x;
    const int c2 = j & 127;
    const int rg8 = (j >> 7) * 8;
    const int row0 = blockIdx.x * 16;
    const int s = row0 / NB;
    const int tx = (s == 0) ? 0 : (s <= 15 ? s : 30 - s);

    for (int r = 0; r < 16; r++) {
        int b = row0 + r - s * NB;
        int w = wid[b * NL + tx];
        for (int k = j; k < 576; k += 256) {
            float v;
            if (k < 256) v = emb[w * NH + k];
            else if (k < 512) {
                int kk = k - 256;
                if (s == 0) v = 0.f;
                else if (s <= 15) v = g_mfwd[(s - 1) * NB * NH + b * NH + kk];
                else {
                    int jj = 30 - s;
                    v = g_mrev[jj * NB * NH + b * NH + kk];
                    if (jj > 0) v += g_mfwd[(jj - 1) * NB * NH + b * NH + kk];
                }
            } else v = tree[b * NLAT + (k - 512)];
            a[r * 576 + k] = v;
        }
    }
    __syncthreads();

    const ulonglong2* A2 = (const ulonglong2*)a;   // row stride 144
    unsigned long long acc[16];
    #pragma unroll
    for (int i = 0; i < 16; i++) acc[i] = 0ULL;
    #pragma unroll 2
    for (int kk = 0; kk < 144; kk++) {
        ulonglong2 w0 = g_Up4[kk * NH + c2];
        ulonglong2 w1 = g_Up4[kk * NH + c2 + 128];
        #pragma unroll
        for (int r = 0; r < 8; r++) {
            ulonglong2 av = A2[(rg8 + r) * 144 + kk];
            FFMA2(acc[r], av.x, w0.x);     FFMA2(acc[r], av.y, w0.y);
            FFMA2(acc[8 + r], av.x, w1.x); FFMA2(acc[8 + r], av.y, w1.y);
        }
    }
    {
        const float b0 = Ub[c2], b1 = Ub[c2 + 128];
        #pragma unroll
        for (int r = 0; r < 8; r++) {
            float2 t0 = unpack2(acc[r]);
            float2 t1 = unpack2(acc[8 + r]);
            hid[(rg8 + r) * NH + c2]       = fmaxf(t0.x + t0.y + b0, 0.f);
            hid[(rg8 + r) * NH + c2 + 128] = fmaxf(t1.x + t1.y + b1, 0.f);
        }
    }
    __syncthreads();

    const int warp = j >> 5, lane = j & 31;
    const float ptv = (s < 15) ? 1.f : 0.f;
    for (int rr = 0; rr < 2; rr++) {
        int r = warp + rr * 8;
        float ps = 0.f;
        for (int c = lane; c < NH; c += 32) ps += hid[r * NH + c] * Usw[c];
        for (int off = 16; off; off >>= 1) ps += __shfl_xor_sync(0xffffffffu, ps, off);
        if (lane == 0) {
            float p = ps + Usb[0];
            float loss = fmaxf(p, 0.f) + log1pf(expf(-fabsf(p))) - p * ptv;
            s_red[r] = loss;
            s_cnt[r] = ((p > 0.f) == (ptv > 0.5f)) ? 1 : 0;
        }
    }
    __syncthreads();
    if (j == 0) {
        double sum = 0.0; unsigned long long c = 0;
        for (int r = 0; r < 16; r++) { sum += (double)s_red[r]; c += (unsigned long long)s_cnt[r]; }
        atomicAdd(&g_ploss, sum);
        atomicAdd(&g_pcnt, c);
    }
}

// ---------------- finalize ----------------
__global__ void k_fin(float* __restrict__ out) {
    out[0] = (float)(g_qloss / (double)NB);
    out[1] = (float)(g_ploss / (double)NB);
    out[2] = (float)((double)g_qcnt / (double)(NL * NB));
    out[3] = (float)((double)g_pcnt / (double)((2 * NL - 1) * NB));
}

extern "C" void kernel_launch(void* const* d_in, const int* in_sizes, int n_in,
                              void* d_out, int out_size) {
    const int*   wid  = (const int*)  d_in[0];
    const float* tree = (const float*)d_in[1];
    const float* emb  = (const float*)d_in[2];
    const float* Wz_w = (const float*)d_in[3];
    const float* Wz_b = (const float*)d_in[4];
    const float* Wr_w = (const float*)d_in[5];
    const float* Ur_w = (const float*)d_in[6];
    const float* Ur_b = (const float*)d_in[7];
    const float* Wh_w = (const float*)d_in[8];
    const float* Wh_b = (const float*)d_in[9];
    const float* W_w  = (const float*)d_in[10];
    const float* W_b  = (const float*)d_in[11];
    const float* U_w  = (const float*)d_in[12];
    const float* U_b  = (const float*)d_in[13];
    const float* Wo_w = (const float*)d_in[14];
    const float* Wo_b = (const float*)d_in[15];
    const float* Us_w = (const float*)d_in[16];
    const float* Us_b = (const float*)d_in[17];
    float* out = (float*)d_out;

    const int q_smem = (16 * NH + 16 * NVP) * 4;       // 81920 B
    const int p_smem = (16 * 576 + 16 * NH) * 4;       // 53248 B
    cudaFuncSetAttribute(k_q, cudaFuncAttributeMaxDynamicSharedMemorySize, q_smem);
    cudaFuncSetAttribute(k_p, cudaFuncAttributeMaxDynamicSharedMemorySize, p_smem);

    k_init<<<1, 32>>>();

    const int total = 256 * 512 * 2 + 256 * 256 * 2 + 256 * 320 + 256 * 576 + NVP * 256;
    k_repack_all<<<(total + 255) / 256, 256>>>(Wz_w, Wh_w, Wr_w, Ur_w, W_w, U_w, Wo_w);

    for (int t = 0; t < STEPS; t++)
        k_gru<<<512, 256>>>(wid, emb, Wz_b, Wh_b, Ur_b, t);

    k_q<<<(NL * NB) / 16, 256, q_smem>>>(wid, tree, W_b, Wo_b);
    k_p<<<((2 * NL - 1) * NB) / 16, 256, p_smem>>>(wid, tree, emb, U_b, Us_w, Us_b);
    k_fin<<<1, 1>>>(out);
}